// round 2
// baseline (speedup 1.0000x reference)
#include <cuda_runtime.h>

#define B_   8
#define C_   64
#define N_   4096
#define K_   20
#define M_   8
#define OUTC 64
#define CM   512   // C_*M_
#define NEG_SLOPE 0.2f

// Scratch (device globals; no dynamic allocation allowed)
__device__ float g_ft[B_ * N_ * C_];                 // feature transposed (B,N,C) : 8 MB
__device__ float g_agg[(size_t)B_ * N_ * CM];        // agg (B*N, 512)             : 64 MB
__device__ int   g_idx_is64;                         // 1 if neigh_indexs is int64

// ----------------------------------------------------------------------------
// Kernel 0: detect index dtype. For int64 nonneg values < 2^31, every odd
// int32 word is 0. 32 consecutive zero odd-words with random int32 indices
// has probability ~(1/4096)^32 — effectively impossible.
// ----------------------------------------------------------------------------
__global__ void detect_kernel(const int* __restrict__ raw) {
    int all0 = 1;
#pragma unroll
    for (int j = 1; j < 64; j += 2)
        if (raw[j] != 0) all0 = 0;
    g_idx_is64 = all0;
}

// ----------------------------------------------------------------------------
// Kernel 1: transpose feature (B,C,N) -> g_ft (B,N,C), both sides coalesced
// ----------------------------------------------------------------------------
__global__ void transpose_kernel(const float* __restrict__ feature) {
    __shared__ float tile[32][33];
    int b  = blockIdx.z;
    int n0 = blockIdx.x * 32;
    int c0 = blockIdx.y * 32;
    int tx = threadIdx.x, ty = threadIdx.y;
#pragma unroll
    for (int i = 0; i < 4; i++) {
        int c = c0 + ty + i * 8;
        tile[ty + i * 8][tx] = feature[((size_t)b * C_ + c) * N_ + n0 + tx];
    }
    __syncthreads();
#pragma unroll
    for (int i = 0; i < 4; i++) {
        int n = n0 + ty + i * 8;
        g_ft[((size_t)b * N_ + n) * C_ + c0 + tx] = tile[tx][ty + i * 8];
    }
}

// ----------------------------------------------------------------------------
// Kernel 2: per-point perm + softmax + agg.
// 256 threads, 4 points per CTA (64 threads per point = one per channel c).
// agg[c][m] = sum_k ft[idx[k]][c] * softmax_k(perm)[k][m]  -> g_agg[q][c*8+m]
// ----------------------------------------------------------------------------
__global__ void agg_kernel(const float* __restrict__ x,
                           const void* __restrict__ nidx,
                           const float* __restrict__ kern) {
    __shared__ int   sIdx[4][K_];
    __shared__ float sX[4][K_][3];
    __shared__ __align__(16) float sP[4][K_][M_];
    __shared__ float sKer[3 * M_];

    int t  = threadIdx.x;
    int q0 = blockIdx.x * 4;
    int is64 = g_idx_is64;

    if (t < 3 * M_) sKer[t] = kern[t];

    if (t < 4 * K_) {
        int g = t / K_, k = t % K_;
        int q = q0 + g;
        int b = q >> 12;
        size_t pos = (size_t)q * K_ + k;
        int i;
        if (is64) i = (int)((const long long*)nidx)[pos];
        else      i = ((const int*)nidx)[pos];
        i &= (N_ - 1);   // safety clamp (no-op for valid indices)
        sIdx[g][k] = i;
        const float* xb = x + (size_t)b * 3 * N_;
        sX[g][k][0] = xb[i];
        sX[g][k][1] = xb[N_ + i];
        sX[g][k][2] = xb[2 * N_ + i];
    }
    __syncthreads();

    if (t < 4 * K_) {
        int g = t / K_, k = t % K_;
        float x0 = sX[g][k][0] - sX[g][0][0];
        float x1 = sX[g][k][1] - sX[g][0][1];
        float x2 = sX[g][k][2] - sX[g][0][2];
#pragma unroll
        for (int m = 0; m < M_; m++) {
            float v = x0 * sKer[m] + x1 * sKer[M_ + m] + x2 * sKer[2 * M_ + m];
            if (k == 0 && m == 0) v += 1.0f;
            sP[g][k][m] = v;
        }
    }
    __syncthreads();

    if (t < 4 * M_) {   // softmax over k, per (point, m)
        int g = t / M_, m = t % M_;
        float mx = -1e30f;
#pragma unroll
        for (int k = 0; k < K_; k++) mx = fmaxf(mx, sP[g][k][m]);
        float s = 0.0f;
#pragma unroll
        for (int k = 0; k < K_; k++) {
            float e = __expf(sP[g][k][m] - mx);
            sP[g][k][m] = e;
            s += e;
        }
        float inv = 1.0f / s;
#pragma unroll
        for (int k = 0; k < K_; k++) sP[g][k][m] *= inv;
    }
    __syncthreads();

    int g = t >> 6, c = t & 63;
    int q = q0 + g;
    int b = q >> 12;
    float acc[M_];
#pragma unroll
    for (int m = 0; m < M_; m++) acc[m] = 0.0f;

    const float* ftb = g_ft + (size_t)b * N_ * C_;
#pragma unroll 4
    for (int k = 0; k < K_; k++) {
        float f = ftb[(size_t)sIdx[g][k] * C_ + c];   // coalesced across c
        float4 p0 = *(const float4*)&sP[g][k][0];
        float4 p1 = *(const float4*)&sP[g][k][4];
        acc[0] += f * p0.x; acc[1] += f * p0.y; acc[2] += f * p0.z; acc[3] += f * p0.w;
        acc[4] += f * p1.x; acc[5] += f * p1.y; acc[6] += f * p1.z; acc[7] += f * p1.w;
    }
    float* o = g_agg + (size_t)q * CM + c * M_;
    *(float4*)(o)     = make_float4(acc[0], acc[1], acc[2], acc[3]);
    *(float4*)(o + 4) = make_float4(acc[4], acc[5], acc[6], acc[7]);
}

// ----------------------------------------------------------------------------
// Kernel 3: GEMM  out[64 x 128pts] = W(64x512) . agg_tile^T  + epilogue
// 256 threads, thread tile 4 oc x 8 pts, k-chunks of 16.
// Epilogue: +bias, leaky_relu, +feature residual, coalesced store.
// ----------------------------------------------------------------------------
__global__ void gemm_kernel(const float* __restrict__ W,
                            const float* __restrict__ bias,
                            const float* __restrict__ feature,
                            float* __restrict__ out) {
    __shared__ __align__(16) float sW[16][64];
    __shared__ __align__(16) float sA[16][128];

    int t  = threadIdx.x;
    int q0 = blockIdx.x * 128;
    int tx = t & 15, ty = t >> 4;
    int pt0 = tx * 8, oc0 = ty * 4;

    float acc[4][8];
#pragma unroll
    for (int i = 0; i < 4; i++)
#pragma unroll
        for (int j = 0; j < 8; j++) acc[i][j] = 0.0f;

    for (int k0 = 0; k0 < CM; k0 += 16) {
        {   // load W chunk (64 oc x 16 k), transposed into sW[k][oc]
            int oc = t >> 2;
            int kk = (t & 3) * 4;
            float4 w = *(const float4*)&W[(size_t)oc * CM + k0 + kk];
            sW[kk][oc] = w.x; sW[kk + 1][oc] = w.y;
            sW[kk + 2][oc] = w.z; sW[kk + 3][oc] = w.w;
        }
        {   // load agg chunk (128 pts x 16 k), transposed into sA[k][pt]
            int pt = t >> 1;
            int kk = (t & 1) * 8;
            const float* a = g_agg + (size_t)(q0 + pt) * CM + k0 + kk;
            float4 a0 = *(const float4*)(a);
            float4 a1 = *(const float4*)(a + 4);
            sA[kk][pt]     = a0.x; sA[kk + 1][pt] = a0.y;
            sA[kk + 2][pt] = a0.z; sA[kk + 3][pt] = a0.w;
            sA[kk + 4][pt] = a1.x; sA[kk + 5][pt] = a1.y;
            sA[kk + 6][pt] = a1.z; sA[kk + 7][pt] = a1.w;
        }
        __syncthreads();

#pragma unroll
        for (int kk = 0; kk < 16; kk++) {
            float4 w  = *(const float4*)&sW[kk][oc0];
            float4 a0 = *(const float4*)&sA[kk][pt0];
            float4 a1 = *(const float4*)&sA[kk][pt0 + 4];
            float wv[4] = {w.x, w.y, w.z, w.w};
            float av[8] = {a0.x, a0.y, a0.z, a0.w, a1.x, a1.y, a1.z, a1.w};
#pragma unroll
            for (int i = 0; i < 4; i++)
#pragma unroll
                for (int j = 0; j < 8; j++) acc[i][j] += wv[i] * av[j];
        }
        __syncthreads();
    }

    int b  = q0 >> 12;
    int n0 = q0 & (N_ - 1);
#pragma unroll
    for (int i = 0; i < 4; i++) {
        int oc = oc0 + i;
        float bs = bias[oc];
        const float* fp = feature + ((size_t)b * OUTC + oc) * N_ + n0 + pt0;
        float*       op = out     + ((size_t)b * OUTC + oc) * N_ + n0 + pt0;
#pragma unroll
        for (int j = 0; j < 8; j++) {
            float v = acc[i][j] + bs;
            v = (v > 0.0f) ? v : NEG_SLOPE * v;
            op[j] = v + fp[j];
        }
    }
}

// ----------------------------------------------------------------------------
extern "C" void kernel_launch(void* const* d_in, const int* in_sizes, int n_in,
                              void* d_out, int out_size) {
    const float* x       = (const float*)d_in[0];
    const float* feature = (const float*)d_in[1];
    const void*  nidx    = d_in[2];
    const float* kern    = (const float*)d_in[3];
    const float* W       = (const float*)d_in[4];
    const float* bias    = (const float*)d_in[5];
    float*       out     = (float*)d_out;

    detect_kernel<<<1, 1>>>((const int*)nidx);
    dim3 tgrid(N_ / 32, C_ / 32, B_);
    transpose_kernel<<<tgrid, dim3(32, 8)>>>(feature);
    agg_kernel<<<(B_ * N_) / 4, 256>>>(x, nidx, kern);
    gemm_kernel<<<(B_ * N_) / 128, 256>>>(W, bias, feature, out);
}

// round 3
// speedup vs baseline: 1.6636x; 1.6636x over previous
#include <cuda_runtime.h>
#include <cuda_bf16.h>
#include <cstdint>

#define B_   8
#define C_   64
#define N_   4096
#define K_   20
#define M_   8
#define OUTC 64
#define CM   512   // C_*M_
#define NEG_SLOPE 0.2f

// Scratch (device globals; no dynamic allocation allowed)
__device__ float           g_ft[B_ * N_ * C_];                    // feature (B,N,C)   : 8 MB
__device__ __nv_bfloat16   g_agg_hi[(size_t)B_ * N_ * CM];       // agg hi            : 32 MB
__device__ __nv_bfloat16   g_agg_lo[(size_t)B_ * N_ * CM];       // agg lo            : 32 MB
__device__ __nv_bfloat16   g_w_hi[OUTC * CM];                    // W hi              : 64 KB
__device__ __nv_bfloat16   g_w_lo[OUTC * CM];                    // W lo              : 64 KB
__device__ int             g_idx_is64;

// ----------------------------------------------------------------------------
// Kernel 0: detect index dtype (int64 vs int32)
// ----------------------------------------------------------------------------
__global__ void detect_kernel(const int* __restrict__ raw) {
    int all0 = 1;
#pragma unroll
    for (int j = 1; j < 64; j += 2)
        if (raw[j] != 0) all0 = 0;
    g_idx_is64 = all0;
}

// ----------------------------------------------------------------------------
// Kernel 0b: split conv_w into bf16 hi/lo
// ----------------------------------------------------------------------------
__global__ void convw_kernel(const float* __restrict__ W) {
    int i = blockIdx.x * 256 + threadIdx.x;
    float w = W[i];
    __nv_bfloat16 h = __float2bfloat16(w);
    g_w_hi[i] = h;
    g_w_lo[i] = __float2bfloat16(w - __bfloat162float(h));
}

// ----------------------------------------------------------------------------
// Kernel 1: transpose feature (B,C,N) -> g_ft (B,N,C)
// ----------------------------------------------------------------------------
__global__ void transpose_kernel(const float* __restrict__ feature) {
    __shared__ float tile[32][33];
    int b  = blockIdx.z;
    int n0 = blockIdx.x * 32;
    int c0 = blockIdx.y * 32;
    int tx = threadIdx.x, ty = threadIdx.y;
#pragma unroll
    for (int i = 0; i < 4; i++) {
        int c = c0 + ty + i * 8;
        tile[ty + i * 8][tx] = feature[((size_t)b * C_ + c) * N_ + n0 + tx];
    }
    __syncthreads();
#pragma unroll
    for (int i = 0; i < 4; i++) {
        int n = n0 + ty + i * 8;
        g_ft[((size_t)b * N_ + n) * C_ + c0 + tx] = tile[tx][ty + i * 8];
    }
}

// ----------------------------------------------------------------------------
// Kernel 2: per-point perm + softmax + agg -> bf16 hi/lo
// ----------------------------------------------------------------------------
__global__ void agg_kernel(const float* __restrict__ x,
                           const void* __restrict__ nidx,
                           const float* __restrict__ kern) {
    __shared__ int   sIdx[4][K_];
    __shared__ float sX[4][K_][3];
    __shared__ __align__(16) float sP[4][K_][M_];
    __shared__ float sKer[3 * M_];

    int t  = threadIdx.x;
    int q0 = blockIdx.x * 4;
    int is64 = g_idx_is64;

    if (t < 3 * M_) sKer[t] = kern[t];

    if (t < 4 * K_) {
        int g = t / K_, k = t % K_;
        int q = q0 + g;
        int b = q >> 12;
        size_t pos = (size_t)q * K_ + k;
        int i;
        if (is64) i = (int)((const long long*)nidx)[pos];
        else      i = ((const int*)nidx)[pos];
        i &= (N_ - 1);
        sIdx[g][k] = i;
        const float* xb = x + (size_t)b * 3 * N_;
        sX[g][k][0] = xb[i];
        sX[g][k][1] = xb[N_ + i];
        sX[g][k][2] = xb[2 * N_ + i];
    }
    __syncthreads();

    if (t < 4 * K_) {
        int g = t / K_, k = t % K_;
        float x0 = sX[g][k][0] - sX[g][0][0];
        float x1 = sX[g][k][1] - sX[g][0][1];
        float x2 = sX[g][k][2] - sX[g][0][2];
#pragma unroll
        for (int m = 0; m < M_; m++) {
            float v = x0 * sKer[m] + x1 * sKer[M_ + m] + x2 * sKer[2 * M_ + m];
            if (k == 0 && m == 0) v += 1.0f;
            sP[g][k][m] = v;
        }
    }
    __syncthreads();

    if (t < 4 * M_) {
        int g = t / M_, m = t % M_;
        float mx = -1e30f;
#pragma unroll
        for (int k = 0; k < K_; k++) mx = fmaxf(mx, sP[g][k][m]);
        float s = 0.0f;
#pragma unroll
        for (int k = 0; k < K_; k++) {
            float e = __expf(sP[g][k][m] - mx);
            sP[g][k][m] = e;
            s += e;
        }
        float inv = 1.0f / s;
#pragma unroll
        for (int k = 0; k < K_; k++) sP[g][k][m] *= inv;
    }
    __syncthreads();

    int g = t >> 6, c = t & 63;
    int q = q0 + g;
    int b = q >> 12;
    float acc[M_];
#pragma unroll
    for (int m = 0; m < M_; m++) acc[m] = 0.0f;

    const float* ftb = g_ft + (size_t)b * N_ * C_;
#pragma unroll 4
    for (int k = 0; k < K_; k++) {
        float f = ftb[(size_t)sIdx[g][k] * C_ + c];
        float4 p0 = *(const float4*)&sP[g][k][0];
        float4 p1 = *(const float4*)&sP[g][k][4];
        acc[0] += f * p0.x; acc[1] += f * p0.y; acc[2] += f * p0.z; acc[3] += f * p0.w;
        acc[4] += f * p1.x; acc[5] += f * p1.y; acc[6] += f * p1.z; acc[7] += f * p1.w;
    }

    // split to bf16 hi/lo, pack 8 x bf16 = 16 B per array
    uint32_t hp[4], lp[4];
#pragma unroll
    for (int m = 0; m < 4; m++) {
        __nv_bfloat16 h0 = __float2bfloat16(acc[2 * m]);
        __nv_bfloat16 h1 = __float2bfloat16(acc[2 * m + 1]);
        __nv_bfloat16 l0 = __float2bfloat16(acc[2 * m]     - __bfloat162float(h0));
        __nv_bfloat16 l1 = __float2bfloat16(acc[2 * m + 1] - __bfloat162float(h1));
        hp[m] = ((uint32_t)__bfloat16_as_ushort(h1) << 16) | __bfloat16_as_ushort(h0);
        lp[m] = ((uint32_t)__bfloat16_as_ushort(l1) << 16) | __bfloat16_as_ushort(l0);
    }
    size_t o = (size_t)q * CM + c * M_;
    *(uint4*)(&g_agg_hi[o]) = make_uint4(hp[0], hp[1], hp[2], hp[3]);
    *(uint4*)(&g_agg_lo[o]) = make_uint4(lp[0], lp[1], lp[2], lp[3]);
}

// ----------------------------------------------------------------------------
// Kernel 3: tensor-core GEMM  D[pt=128][oc=64] = Agg(128xK) . W(64xK)^T
// mma.sync.m16n8k16 bf16, 3-term split, fp32 accum. 8 warps, warp tile 32x32.
// ----------------------------------------------------------------------------
#define KC     32               // k per stage
#define ASTR   40               // smem row stride (bf16 elems): 80B, 16B-aligned, conflict-free
#define SOS    132              // epilogue smem row stride (floats)

#define LDSM4(R0, R1, R2, R3, addr)                                        \
    asm volatile("ldmatrix.sync.aligned.m8n8.x4.shared.b16 {%0,%1,%2,%3}, [%4];" \
                 : "=r"(R0), "=r"(R1), "=r"(R2), "=r"(R3) : "r"(addr))

#define MMA(d, a, b0v, b1v)                                                \
    asm volatile("mma.sync.aligned.m16n8k16.row.col.f32.bf16.bf16.f32 "    \
                 "{%0,%1,%2,%3}, {%4,%5,%6,%7}, {%8,%9}, {%0,%1,%2,%3};"   \
                 : "+f"(d[0]), "+f"(d[1]), "+f"(d[2]), "+f"(d[3])          \
                 : "r"(a[0]), "r"(a[1]), "r"(a[2]), "r"(a[3]),             \
                   "r"(b0v), "r"(b1v))

__global__ void __launch_bounds__(256)
gemm_kernel(const float* __restrict__ bias,
            const float* __restrict__ feature,
            float* __restrict__ out) {
    __shared__ __align__(16) unsigned char smem_raw[64 * SOS * 4];  // 33792 B

    __nv_bfloat16* sAh = (__nv_bfloat16*)(smem_raw);                 // 128*40*2 = 10240
    __nv_bfloat16* sAl = (__nv_bfloat16*)(smem_raw + 10240);         // 10240
    __nv_bfloat16* sWh = (__nv_bfloat16*)(smem_raw + 20480);         // 64*40*2 = 5120
    __nv_bfloat16* sWl = (__nv_bfloat16*)(smem_raw + 25600);         // 5120
    float*         sOut = (float*)smem_raw;                          // 64*132*4

    int t  = threadIdx.x;
    int w  = t >> 5, l = t & 31;
    int q0 = blockIdx.x * 128;
    int b  = q0 >> 12;
    int n0 = q0 & (N_ - 1);

    int mw = w & 3, nw = w >> 2;
    int ptb = mw * 32, ocb = nw * 32;

    float acc[2][4][4];
#pragma unroll
    for (int mi = 0; mi < 2; mi++)
#pragma unroll
        for (int nt = 0; nt < 4; nt++)
#pragma unroll
            for (int j = 0; j < 4; j++) acc[mi][nt][j] = 0.0f;

    // precompute ldmatrix smem addresses (byte offsets fixed per lane)
    uint32_t aBase = (uint32_t)__cvta_generic_to_shared(sAh);
    uint32_t alBase = (uint32_t)__cvta_generic_to_shared(sAl);
    uint32_t wBase = (uint32_t)__cvta_generic_to_shared(sWh);
    uint32_t wlBase = (uint32_t)__cvta_generic_to_shared(sWl);

    int aRow = ptb + (l & 15);             // + mi*16
    int aCol = (l >> 4) * 8;               // + koff
    int bRow = ocb + ((l >> 4) * 8) + (l & 7);  // + ni2*16
    int bCol = ((l >> 3) & 1) * 8;         // + koff

    // global load indices
    int pt_g  = t >> 1;           // 0..127
    int seg_g = (t & 1) * 16;     // k offset within stage
    const __nv_bfloat16* gA_hi = g_agg_hi + (size_t)(q0 + pt_g) * CM + seg_g;
    const __nv_bfloat16* gA_lo = g_agg_lo + (size_t)(q0 + pt_g) * CM + seg_g;
    __nv_bfloat16* dAh = sAh + pt_g * ASTR + seg_g;
    __nv_bfloat16* dAl = sAl + pt_g * ASTR + seg_g;
    int oc_g = t >> 1;            // 0..127 but only t<128 loads W (oc 0..63)
    const __nv_bfloat16* gW_hi = g_w_hi + (size_t)oc_g * CM + seg_g;
    const __nv_bfloat16* gW_lo = g_w_lo + (size_t)oc_g * CM + seg_g;
    __nv_bfloat16* dWh = sWh + oc_g * ASTR + seg_g;
    __nv_bfloat16* dWl = sWl + oc_g * ASTR + seg_g;

    for (int s = 0; s < CM / KC; s++) {
        int ks = s * KC;
        // stage loads
        *(uint4*)dAh = *(const uint4*)(gA_hi + ks);
        *(uint4*)(dAh + 8) = *(const uint4*)(gA_hi + ks + 8);
        *(uint4*)dAl = *(const uint4*)(gA_lo + ks);
        *(uint4*)(dAl + 8) = *(const uint4*)(gA_lo + ks + 8);
        if (t < 128) {
            *(uint4*)dWh = *(const uint4*)(gW_hi + ks);
            *(uint4*)(dWh + 8) = *(const uint4*)(gW_hi + ks + 8);
            *(uint4*)dWl = *(const uint4*)(gW_lo + ks);
            *(uint4*)(dWl + 8) = *(const uint4*)(gW_lo + ks + 8);
        }
        __syncthreads();

#pragma unroll
        for (int step = 0; step < 2; step++) {
            int koff = step * 16;
            uint32_t Ah[2][4], Al[2][4], Bh[2][4], Bl[2][4];
#pragma unroll
            for (int mi = 0; mi < 2; mi++) {
                uint32_t off = ((aRow + mi * 16) * ASTR + aCol + koff) * 2;
                LDSM4(Ah[mi][0], Ah[mi][1], Ah[mi][2], Ah[mi][3], aBase + off);
                LDSM4(Al[mi][0], Al[mi][1], Al[mi][2], Al[mi][3], alBase + off);
            }
#pragma unroll
            for (int ni2 = 0; ni2 < 2; ni2++) {
                uint32_t off = ((bRow + ni2 * 16) * ASTR + bCol + koff) * 2;
                LDSM4(Bh[ni2][0], Bh[ni2][1], Bh[ni2][2], Bh[ni2][3], wBase + off);
                LDSM4(Bl[ni2][0], Bl[ni2][1], Bl[ni2][2], Bl[ni2][3], wlBase + off);
            }
#pragma unroll
            for (int mi = 0; mi < 2; mi++) {
#pragma unroll
                for (int nt = 0; nt < 4; nt++) {
                    int ni2 = nt >> 1, sel = (nt & 1) * 2;
                    MMA(acc[mi][nt], Ah[mi], Bh[ni2][sel], Bh[ni2][sel + 1]);
                    MMA(acc[mi][nt], Ah[mi], Bl[ni2][sel], Bl[ni2][sel + 1]);
                    MMA(acc[mi][nt], Al[mi], Bh[ni2][sel], Bh[ni2][sel + 1]);
                }
            }
        }
        __syncthreads();
    }

    // epilogue: stage D (pt x oc) into smem as [oc][pt] then coalesced store
    int g2 = l >> 2, t4 = l & 3;
#pragma unroll
    for (int mi = 0; mi < 2; mi++) {
#pragma unroll
        for (int nt = 0; nt < 4; nt++) {
            int pt = ptb + mi * 16 + g2;
            int oc = ocb + nt * 8 + 2 * t4;
            sOut[oc * SOS + pt]           = acc[mi][nt][0];
            sOut[(oc + 1) * SOS + pt]     = acc[mi][nt][1];
            sOut[oc * SOS + pt + 8]       = acc[mi][nt][2];
            sOut[(oc + 1) * SOS + pt + 8] = acc[mi][nt][3];
        }
    }
    __syncthreads();

#pragma unroll
    for (int r = 0; r < 8; r++) {
        int oc = w * 8 + r;
        float bs = bias[oc];
        float4 v = *(float4*)&sOut[oc * SOS + l * 4];
        size_t go = ((size_t)(b * OUTC + oc)) * N_ + n0 + l * 4;
        float4 f = *(const float4*)&feature[go];
        v.x += bs; v.x = (v.x > 0.f) ? v.x : NEG_SLOPE * v.x; v.x += f.x;
        v.y += bs; v.y = (v.y > 0.f) ? v.y : NEG_SLOPE * v.y; v.y += f.y;
        v.z += bs; v.z = (v.z > 0.f) ? v.z : NEG_SLOPE * v.z; v.z += f.z;
        v.w += bs; v.w = (v.w > 0.f) ? v.w : NEG_SLOPE * v.w; v.w += f.w;
        *(float4*)&out[go] = v;
    }
}

// ----------------------------------------------------------------------------
extern "C" void kernel_launch(void* const* d_in, const int* in_sizes, int n_in,
                              void* d_out, int out_size) {
    const float* x       = (const float*)d_in[0];
    const float* feature = (const float*)d_in[1];
    const void*  nidx    = d_in[2];
    const float* kern    = (const float*)d_in[3];
    const float* W       = (const float*)d_in[4];
    const float* bias    = (const float*)d_in[5];
    float*       out     = (float*)d_out;

    detect_kernel<<<1, 1>>>((const int*)nidx);
    convw_kernel<<<(OUTC * CM) / 256, 256>>>(W);
    dim3 tgrid(N_ / 32, C_ / 32, B_);
    transpose_kernel<<<tgrid, dim3(32, 8)>>>(feature);
    agg_kernel<<<(B_ * N_) / 4, 256>>>(x, nidx, kern);
    gemm_kernel<<<(B_ * N_) / 128, 256>>>(bias, feature, out);
}

// round 4
// speedup vs baseline: 1.9503x; 1.1724x over previous
#include <cuda_runtime.h>
#include <cuda_bf16.h>
#include <cstdint>

#define B_   8
#define C_   64
#define N_   4096
#define K_   20
#define M_   8
#define OUTC 64
#define CM   512   // C_*M_
#define NEG_SLOPE 0.2f

// Scratch (device globals; no dynamic allocation allowed)
__device__ float           g_ft[B_ * N_ * C_];                    // feature (B,N,C)   : 8 MB
__device__ __nv_bfloat16   g_agg_hi[(size_t)B_ * N_ * CM];       // agg hi            : 32 MB
__device__ __nv_bfloat16   g_agg_lo[(size_t)B_ * N_ * CM];       // agg lo            : 32 MB
__device__ __nv_bfloat16   g_w_hi[OUTC * CM];                    // W hi              : 64 KB
__device__ __nv_bfloat16   g_w_lo[OUTC * CM];                    // W lo              : 64 KB
__device__ int             g_idx_is64;

// ----------------------------------------------------------------------------
// Kernel 0: detect index dtype (int64 vs int32)
// ----------------------------------------------------------------------------
__global__ void detect_kernel(const int* __restrict__ raw) {
    int all0 = 1;
#pragma unroll
    for (int j = 1; j < 64; j += 2)
        if (raw[j] != 0) all0 = 0;
    g_idx_is64 = all0;
}

// ----------------------------------------------------------------------------
// Kernel 0b: split conv_w into bf16 hi/lo
// ----------------------------------------------------------------------------
__global__ void convw_kernel(const float* __restrict__ W) {
    int i = blockIdx.x * 256 + threadIdx.x;
    float w = W[i];
    __nv_bfloat16 h = __float2bfloat16(w);
    g_w_hi[i] = h;
    g_w_lo[i] = __float2bfloat16(w - __bfloat162float(h));
}

// ----------------------------------------------------------------------------
// Kernel 1: transpose feature (B,C,N) -> g_ft (B,N,C)
// ----------------------------------------------------------------------------
__global__ void transpose_kernel(const float* __restrict__ feature) {
    __shared__ float tile[32][33];
    int b  = blockIdx.z;
    int n0 = blockIdx.x * 32;
    int c0 = blockIdx.y * 32;
    int tx = threadIdx.x, ty = threadIdx.y;
#pragma unroll
    for (int i = 0; i < 4; i++) {
        int c = c0 + ty + i * 8;
        tile[ty + i * 8][tx] = feature[((size_t)b * C_ + c) * N_ + n0 + tx];
    }
    __syncthreads();
#pragma unroll
    for (int i = 0; i < 4; i++) {
        int n = n0 + ty + i * 8;
        g_ft[((size_t)b * N_ + n) * C_ + c0 + tx] = tile[tx][ty + i * 8];
    }
}

// ----------------------------------------------------------------------------
// Kernel 2: per-point perm + softmax + agg -> bf16 hi/lo
// 256 threads, 8 points/CTA, 32 threads/point (float2 over channels)
// ----------------------------------------------------------------------------
__global__ void __launch_bounds__(256)
agg_kernel(const float* __restrict__ x,
           const void* __restrict__ nidx,
           const float* __restrict__ kern) {
    __shared__ int   sIdx[8][K_];
    __shared__ float sX[8][K_][3];
    __shared__ __align__(16) float sP[8][K_][M_];
    __shared__ float sKer[3 * M_];

    int t  = threadIdx.x;
    int q0 = blockIdx.x * 8;
    int is64 = g_idx_is64;

    if (t < 3 * M_) sKer[t] = kern[t];

    if (t < 8 * K_) {           // 160 threads: idx + x gather
        int g = t / K_, k = t % K_;
        int q = q0 + g;
        int b = q >> 12;
        size_t pos = (size_t)q * K_ + k;
        int i;
        if (is64) i = (int)((const long long*)nidx)[pos];
        else      i = ((const int*)nidx)[pos];
        i &= (N_ - 1);          // safety clamp (no-op for valid indices)
        sIdx[g][k] = i;
        const float* xb = x + (size_t)b * 3 * N_;
        sX[g][k][0] = xb[i];
        sX[g][k][1] = xb[N_ + i];
        sX[g][k][2] = xb[2 * N_ + i];
    }
    __syncthreads();

    if (t < 8 * K_) {           // perm rows
        int g = t / K_, k = t % K_;
        float x0 = sX[g][k][0] - sX[g][0][0];
        float x1 = sX[g][k][1] - sX[g][0][1];
        float x2 = sX[g][k][2] - sX[g][0][2];
#pragma unroll
        for (int m = 0; m < M_; m++) {
            float v = x0 * sKer[m] + x1 * sKer[M_ + m] + x2 * sKer[2 * M_ + m];
            if (k == 0 && m == 0) v += 1.0f;
            sP[g][k][m] = v;
        }
    }
    __syncthreads();

    if (t < 8 * M_) {           // softmax over k per (point, m): 64 threads
        int g = t >> 3, m = t & 7;
        float mx = -1e30f;
#pragma unroll
        for (int k = 0; k < K_; k++) mx = fmaxf(mx, sP[g][k][m]);
        float s = 0.0f;
#pragma unroll
        for (int k = 0; k < K_; k++) {
            float e = __expf(sP[g][k][m] - mx);
            sP[g][k][m] = e;
            s += e;
        }
        float inv = 1.0f / s;
#pragma unroll
        for (int k = 0; k < K_; k++) sP[g][k][m] *= inv;
    }
    __syncthreads();

    // main: warp g handles point q0+g; lane covers channels {2l, 2l+1}
    int g = t >> 5, lane = t & 31;
    int q = q0 + g;
    int b = q >> 12;

    float acc0[M_], acc1[M_];
#pragma unroll
    for (int m = 0; m < M_; m++) { acc0[m] = 0.0f; acc1[m] = 0.0f; }

    const float* ftb = g_ft + (size_t)b * N_ * C_ + 2 * lane;
#pragma unroll
    for (int k = 0; k < K_; k++) {
        float2 f = *(const float2*)(ftb + (size_t)sIdx[g][k] * C_);
        float4 p0 = *(const float4*)&sP[g][k][0];
        float4 p1 = *(const float4*)&sP[g][k][4];
        acc0[0] += f.x * p0.x; acc0[1] += f.x * p0.y; acc0[2] += f.x * p0.z; acc0[3] += f.x * p0.w;
        acc0[4] += f.x * p1.x; acc0[5] += f.x * p1.y; acc0[6] += f.x * p1.z; acc0[7] += f.x * p1.w;
        acc1[0] += f.y * p0.x; acc1[1] += f.y * p0.y; acc1[2] += f.y * p0.z; acc1[3] += f.y * p0.w;
        acc1[4] += f.y * p1.x; acc1[5] += f.y * p1.y; acc1[6] += f.y * p1.z; acc1[7] += f.y * p1.w;
    }

    // split to bf16 hi/lo; this thread owns 16 consecutive output elems
    uint32_t hp[8], lp[8];
#pragma unroll
    for (int m = 0; m < 4; m++) {
        __nv_bfloat16 h0 = __float2bfloat16(acc0[2 * m]);
        __nv_bfloat16 h1 = __float2bfloat16(acc0[2 * m + 1]);
        __nv_bfloat16 l0 = __float2bfloat16(acc0[2 * m]     - __bfloat162float(h0));
        __nv_bfloat16 l1 = __float2bfloat16(acc0[2 * m + 1] - __bfloat162float(h1));
        hp[m] = ((uint32_t)__bfloat16_as_ushort(h1) << 16) | __bfloat16_as_ushort(h0);
        lp[m] = ((uint32_t)__bfloat16_as_ushort(l1) << 16) | __bfloat16_as_ushort(l0);
        __nv_bfloat16 h2 = __float2bfloat16(acc1[2 * m]);
        __nv_bfloat16 h3 = __float2bfloat16(acc1[2 * m + 1]);
        __nv_bfloat16 l2 = __float2bfloat16(acc1[2 * m]     - __bfloat162float(h2));
        __nv_bfloat16 l3 = __float2bfloat16(acc1[2 * m + 1] - __bfloat162float(h3));
        hp[4 + m] = ((uint32_t)__bfloat16_as_ushort(h3) << 16) | __bfloat16_as_ushort(h2);
        lp[4 + m] = ((uint32_t)__bfloat16_as_ushort(l3) << 16) | __bfloat16_as_ushort(l2);
    }
    size_t o = (size_t)q * CM + (size_t)(2 * lane) * M_;   // 16 elems per thread
    *(uint4*)(&g_agg_hi[o])     = make_uint4(hp[0], hp[1], hp[2], hp[3]);
    *(uint4*)(&g_agg_hi[o + 8]) = make_uint4(hp[4], hp[5], hp[6], hp[7]);
    *(uint4*)(&g_agg_lo[o])     = make_uint4(lp[0], lp[1], lp[2], lp[3]);
    *(uint4*)(&g_agg_lo[o + 8]) = make_uint4(lp[4], lp[5], lp[6], lp[7]);
}

// ----------------------------------------------------------------------------
// Kernel 3: tensor-core GEMM, software-pipelined (double-buffered smem,
// register prefetch, 1 sync/stage). D[128 pts][64 oc], 3-term bf16 split.
// ----------------------------------------------------------------------------
#define KC        32
#define ASTR      40
#define SOS       132
#define BUF_BYTES 30720     // Ah 10240 | Al 10240 | Wh 5120 | Wl 5120
#define OFF_AL    10240
#define OFF_WH    20480
#define OFF_WL    25600
#define NSTAGE    (CM / KC) // 16

#define LDSM4(R0, R1, R2, R3, addr)                                        \
    asm volatile("ldmatrix.sync.aligned.m8n8.x4.shared.b16 {%0,%1,%2,%3}, [%4];" \
                 : "=r"(R0), "=r"(R1), "=r"(R2), "=r"(R3) : "r"(addr))

#define MMA(d, a, b0v, b1v)                                                \
    asm volatile("mma.sync.aligned.m16n8k16.row.col.f32.bf16.bf16.f32 "    \
                 "{%0,%1,%2,%3}, {%4,%5,%6,%7}, {%8,%9}, {%0,%1,%2,%3};"   \
                 : "+f"(d[0]), "+f"(d[1]), "+f"(d[2]), "+f"(d[3])          \
                 : "r"(a[0]), "r"(a[1]), "r"(a[2]), "r"(a[3]),             \
                   "r"(b0v), "r"(b1v))

#define LOADG(s) do { int ks_ = (s) * KC;                                  \
    rAh0 = *(const uint4*)(gA_hi + ks_); rAh1 = *(const uint4*)(gA_hi + ks_ + 8); \
    rAl0 = *(const uint4*)(gA_lo + ks_); rAl1 = *(const uint4*)(gA_lo + ks_ + 8); \
    if (t < 128) {                                                         \
        rWh0 = *(const uint4*)(gW_hi + ks_); rWh1 = *(const uint4*)(gW_hi + ks_ + 8); \
        rWl0 = *(const uint4*)(gW_lo + ks_); rWl1 = *(const uint4*)(gW_lo + ks_ + 8); \
    } } while (0)

#define STORES(bufi) do { unsigned char* bb_ = smem_raw + (bufi) * BUF_BYTES; \
    *(uint4*)(bb_ + stA)              = rAh0; *(uint4*)(bb_ + stA + 16)              = rAh1; \
    *(uint4*)(bb_ + OFF_AL + stA)     = rAl0; *(uint4*)(bb_ + OFF_AL + stA + 16)     = rAl1; \
    if (t < 128) {                                                         \
        *(uint4*)(bb_ + OFF_WH + stW) = rWh0; *(uint4*)(bb_ + OFF_WH + stW + 16) = rWh1; \
        *(uint4*)(bb_ + OFF_WL + stW) = rWl0; *(uint4*)(bb_ + OFF_WL + stW + 16) = rWl1; \
    } } while (0)

extern __shared__ unsigned char g_dsm[];

__global__ void __launch_bounds__(256)
gemm_kernel(const float* __restrict__ bias,
            const float* __restrict__ feature,
            float* __restrict__ out) {
    unsigned char* smem_raw = g_dsm;
    float* sOut = (float*)g_dsm;

    int t  = threadIdx.x;
    int w  = t >> 5, l = t & 31;
    int q0 = blockIdx.x * 128;
    int b  = q0 >> 12;
    int n0 = q0 & (N_ - 1);

    int mw = w & 3, nw = w >> 2;
    int ptb = mw * 32, ocb = nw * 32;

    float acc[2][4][4];
#pragma unroll
    for (int mi = 0; mi < 2; mi++)
#pragma unroll
        for (int nt = 0; nt < 4; nt++)
#pragma unroll
            for (int j = 0; j < 4; j++) acc[mi][nt][j] = 0.0f;

    uint32_t smemBase = (uint32_t)__cvta_generic_to_shared(g_dsm);

    int aRow = ptb + (l & 15);
    int aCol = (l >> 4) * 8;
    int bRow = ocb + ((l >> 4) * 8) + (l & 7);
    int bCol = ((l >> 3) & 1) * 8;

    int pt_g  = t >> 1;
    int seg_g = (t & 1) * 16;
    const __nv_bfloat16* gA_hi = g_agg_hi + (size_t)(q0 + pt_g) * CM + seg_g;
    const __nv_bfloat16* gA_lo = g_agg_lo + (size_t)(q0 + pt_g) * CM + seg_g;
    const __nv_bfloat16* gW_hi = g_w_hi + (size_t)pt_g * CM + seg_g;   // t<128 -> oc 0..63
    const __nv_bfloat16* gW_lo = g_w_lo + (size_t)pt_g * CM + seg_g;
    uint32_t stA = (uint32_t)(pt_g * ASTR + seg_g) * 2;
    uint32_t stW = stA;

    uint4 rAh0, rAh1, rAl0, rAl1, rWh0, rWh1, rWl0, rWl1;

    LOADG(0);
    STORES(0);
    __syncthreads();

    for (int s = 0; s < NSTAGE; s++) {
        int buf = s & 1;
        if (s + 1 < NSTAGE) LOADG(s + 1);

        uint32_t base = smemBase + buf * BUF_BYTES;
#pragma unroll
        for (int step = 0; step < 2; step++) {
            int koff = step * 16;
            uint32_t Ah[2][4], Al[2][4], Bh[2][4], Bl[2][4];
#pragma unroll
            for (int mi = 0; mi < 2; mi++) {
                uint32_t off = (uint32_t)((aRow + mi * 16) * ASTR + aCol + koff) * 2;
                LDSM4(Ah[mi][0], Ah[mi][1], Ah[mi][2], Ah[mi][3], base + off);
                LDSM4(Al[mi][0], Al[mi][1], Al[mi][2], Al[mi][3], base + OFF_AL + off);
            }
#pragma unroll
            for (int ni2 = 0; ni2 < 2; ni2++) {
                uint32_t off = (uint32_t)((bRow + ni2 * 16) * ASTR + bCol + koff) * 2;
                LDSM4(Bh[ni2][0], Bh[ni2][1], Bh[ni2][2], Bh[ni2][3], base + OFF_WH + off);
                LDSM4(Bl[ni2][0], Bl[ni2][1], Bl[ni2][2], Bl[ni2][3], base + OFF_WL + off);
            }
#pragma unroll
            for (int mi = 0; mi < 2; mi++) {
#pragma unroll
                for (int nt = 0; nt < 4; nt++) {
                    int ni2 = nt >> 1, sel = (nt & 1) * 2;
                    MMA(acc[mi][nt], Ah[mi], Bh[ni2][sel], Bh[ni2][sel + 1]);
                    MMA(acc[mi][nt], Ah[mi], Bl[ni2][sel], Bl[ni2][sel + 1]);
                    MMA(acc[mi][nt], Al[mi], Bh[ni2][sel], Bh[ni2][sel + 1]);
                }
            }
        }

        if (s + 1 < NSTAGE) STORES((s + 1) & 1);   // writes buf^1: safe, last read s-1
        __syncthreads();
    }

    // epilogue: stage D (pt x oc) into smem as [oc][pt], coalesced store
    int g2 = l >> 2, t4 = l & 3;
#pragma unroll
    for (int mi = 0; mi < 2; mi++) {
#pragma unroll
        for (int nt = 0; nt < 4; nt++) {
            int pt = ptb + mi * 16 + g2;
            int oc = ocb + nt * 8 + 2 * t4;
            sOut[oc * SOS + pt]           = acc[mi][nt][0];
            sOut[(oc + 1) * SOS + pt]     = acc[mi][nt][1];
            sOut[oc * SOS + pt + 8]       = acc[mi][nt][2];
            sOut[(oc + 1) * SOS + pt + 8] = acc[mi][nt][3];
        }
    }
    __syncthreads();

#pragma unroll
    for (int r = 0; r < 8; r++) {
        int oc = w * 8 + r;
        float bs = bias[oc];
        float4 v = *(float4*)&sOut[oc * SOS + l * 4];
        size_t go = ((size_t)(b * OUTC + oc)) * N_ + n0 + l * 4;
        float4 f = *(const float4*)&feature[go];
        v.x += bs; v.x = (v.x > 0.f) ? v.x : NEG_SLOPE * v.x; v.x += f.x;
        v.y += bs; v.y = (v.y > 0.f) ? v.y : NEG_SLOPE * v.y; v.y += f.y;
        v.z += bs; v.z = (v.z > 0.f) ? v.z : NEG_SLOPE * v.z; v.z += f.z;
        v.w += bs; v.w = (v.w > 0.f) ? v.w : NEG_SLOPE * v.w; v.w += f.w;
        *(float4*)&out[go] = v;
    }
}

// ----------------------------------------------------------------------------
extern "C" void kernel_launch(void* const* d_in, const int* in_sizes, int n_in,
                              void* d_out, int out_size) {
    const float* x       = (const float*)d_in[0];
    const float* feature = (const float*)d_in[1];
    const void*  nidx    = d_in[2];
    const float* kern    = (const float*)d_in[3];
    const float* W       = (const float*)d_in[4];
    const float* bias    = (const float*)d_in[5];
    float*       out     = (float*)d_out;

    cudaFuncSetAttribute(gemm_kernel,
                         cudaFuncAttributeMaxDynamicSharedMemorySize,
                         2 * BUF_BYTES);

    detect_kernel<<<1, 1>>>((const int*)nidx);
    convw_kernel<<<(OUTC * CM) / 256, 256>>>(W);
    dim3 tgrid(N_ / 32, C_ / 32, B_);
    transpose_kernel<<<tgrid, dim3(32, 8)>>>(feature);
    agg_kernel<<<(B_ * N_) / 8, 256>>>(x, nidx, kern);
    gemm_kernel<<<(B_ * N_) / 128, 256, 2 * BUF_BYTES>>>(bias, feature, out);
}